// round 7
// baseline (speedup 1.0000x reference)
#include <cuda_runtime.h>
#include <cuda_bf16.h>
#include <cstdint>

#define NN 20000
#define NE 320000
#define FN 64
#define FE 16
#define HID 300
#define NDEPTH 3
#define NG 128

// SIMT GEMM tiles (init / e2n)
#define TM 64
#define TN 64
#define TK 16

// conv MMA tiles
#define CBM 128
#define CBN 160
#define CBK 32
#define KPAD 320
#define NPR 320            // W rows padded (HID=300 -> 320)
#define NKB (KPAD / CBK)   // 10
#define ASTR 40            // padded k-stride in halfs

// dynamic smem layout (halfs, per stage): Ah[128*40] Al[128*40] Bh[160*40] Bl[160*40]
#define ST_HALFS 23040
#define OFF_AL 5120
#define OFF_BH 10240
#define OFF_BL 16640
#define SMEM_BYTES (2 * ST_HALFS * 2)

// ---------------- static scratch (no runtime allocation allowed) ----------------
__device__ __align__(256) float g_h0[(size_t)NE * HID];
__device__ __align__(256) float g_hA[(size_t)NE * HID];
__device__ __align__(256) float g_hB[(size_t)NE * HID];
__device__ __align__(256) float g_a [(size_t)NN * HID];
__device__ __align__(256) float g_hn[(size_t)NN * HID];
__device__ __align__(256) float g_pool[(size_t)NG * HID];
__device__ __align__(256) uint16_t g_WhiT[(size_t)NDEPTH * NPR * KPAD];
__device__ __align__(256) uint16_t g_WloT[(size_t)NDEPTH * NPR * KPAD];

// ---------------- helpers ----------------
__device__ __forceinline__ uint16_t f2bf_bits(float v) {
    __nv_bfloat16 b = __float2bfloat16(v);
    return *reinterpret_cast<uint16_t*>(&b);
}
__device__ __forceinline__ float bf_bits2f(uint16_t u) {
    __nv_bfloat16 b = *reinterpret_cast<__nv_bfloat16*>(&u);
    return __bfloat162float(b);
}

__device__ __forceinline__ void mma_bf16(float* d, const uint32_t* a,
                                         uint32_t b0, uint32_t b1) {
    asm volatile(
        "mma.sync.aligned.m16n8k16.row.col.f32.bf16.bf16.f32 "
        "{%0,%1,%2,%3}, {%4,%5,%6,%7}, {%8,%9}, {%0,%1,%2,%3};"
        : "+f"(d[0]), "+f"(d[1]), "+f"(d[2]), "+f"(d[3])
        : "r"(a[0]), "r"(a[1]), "r"(a[2]), "r"(a[3]), "r"(b0), "r"(b1));
}

__device__ __forceinline__ void cp16(uint32_t dst_smem, const void* src) {
    asm volatile("cp.async.cg.shared.global [%0], [%1], 16;" ::
                 "r"(dst_smem), "l"(src));
}
__device__ __forceinline__ void cp_commit() {
    asm volatile("cp.async.commit_group;");
}
__device__ __forceinline__ void cp_wait0() {
    asm volatile("cp.async.wait_group 0;");
}

__device__ __forceinline__ void red_v4(float* dst, float4 v) {
    asm volatile("red.global.add.v4.f32 [%0], {%1,%2,%3,%4};" ::
                 "l"(dst), "f"(v.x), "f"(v.y), "f"(v.z), "f"(v.w) : "memory");
}

// ---------------- utility kernels ----------------
__global__ void k_zero(float4* p, int n4) {
    int i = blockIdx.x * blockDim.x + threadIdx.x;
    if (i < n4) p[i] = make_float4(0.f, 0.f, 0.f, 0.f);
}

// split W_convs into transposed, padded bf16 hi/lo: W_T[l][n][k], n padded to 320
__global__ void k_splitW(const float* __restrict__ W,
                         uint16_t* __restrict__ WhiT, uint16_t* __restrict__ WloT) {
    int idx = blockIdx.x * blockDim.x + threadIdx.x;
    const int total = NDEPTH * NPR * KPAD;
    if (idx >= total) return;
    int l = idx / (NPR * KPAD);
    int rem = idx - l * (NPR * KPAD);
    int n = rem / KPAD;
    int k = rem - n * KPAD;
    float v = (k < HID && n < HID) ? W[(size_t)l * HID * HID + (size_t)k * HID + n] : 0.f;
    uint16_t hb = f2bf_bits(v);
    float lo = v - bf_bits2f(hb);
    WhiT[idx] = hb;
    WloT[idx] = f2bf_bits(lo);
}

// segment_sum over edges: a[col[e]] += h[e]
__global__ void k_scatter_edges(const float4* __restrict__ h4,
                                const int* __restrict__ col,
                                float* __restrict__ a) {
    int t = blockIdx.x * blockDim.x + threadIdx.x;
    const int total = NE * (HID / 4);
    if (t >= total) return;
    int e = t / (HID / 4);
    int c = t - e * (HID / 4);
    float4 v = h4[t];
    float* dst = a + (size_t)__ldg(col + e) * HID + (c << 2);
    red_v4(dst, v);
}

// pooled[batch[n]] += hn[n]
__global__ void k_scatter_pool(const float4* __restrict__ hn4,
                               const int* __restrict__ batch,
                               float* __restrict__ pool) {
    int t = blockIdx.x * blockDim.x + threadIdx.x;
    const int total = NN * (HID / 4);
    if (t >= total) return;
    int n = t / (HID / 4);
    int c = t - n * (HID / 4);
    float4 v = hn4[t];
    float* dst = pool + (size_t)__ldg(batch + n) * HID + (c << 2);
    red_v4(dst, v);
}

__global__ void k_ffn(const float* __restrict__ pool, const float* __restrict__ W,
                      const float* __restrict__ b, float* __restrict__ out) {
    __shared__ float red[128];
    int g = blockIdx.x;
    float s = 0.f;
    for (int j = threadIdx.x; j < HID; j += 128)
        s += pool[(size_t)g * HID + j] * W[j];
    red[threadIdx.x] = s;
    __syncthreads();
    for (int k = 64; k > 0; k >>= 1) {
        if (threadIdx.x < k) red[threadIdx.x] += red[threadIdx.x + k];
        __syncthreads();
    }
    if (threadIdx.x == 0) out[g] = red[0] + b[0];
}

// ---------------- conv layer via tensor cores (split-bf16, 3-MMA) ----------------
// out[e] = relu((a[row[e]] - h[e^1]) @ W + b + h0[e])
// Double-buffered dynamic smem; W via cp.async; A via reg-stage + split-convert.
__global__ void __launch_bounds__(256, 2) k_conv_mma(
    const float* __restrict__ a, const float* __restrict__ h,
    const float* __restrict__ h0, const uint16_t* __restrict__ WhiT,
    const uint16_t* __restrict__ WloT, const float* __restrict__ bias,
    const int* __restrict__ row, float* __restrict__ out)
{
    extern __shared__ uint16_t smem[];
    __shared__ int rows_s[CBM];

    const int tid = threadIdx.x;
    const int eb = blockIdx.y * CBM;
    const int jb = blockIdx.x * CBN;

    uint32_t smem_u32;
    {
        uint64_t tmp;
        asm("cvta.to.shared.u64 %0, %1;" : "=l"(tmp) : "l"((const void*)smem));
        smem_u32 = (uint32_t)tmp;
    }

    if (tid < CBM) rows_s[tid] = __ldg(row + eb + tid);
    __syncthreads();

    // A staging: thread covers row ai, 16 consecutive k at ak0
    const int ai = tid >> 1;
    const int ak0 = (tid & 1) << 4;
    const float* ap = a + (size_t)rows_s[ai] * HID;
    const float* hp = h + (size_t)((eb + ai) ^ 1) * HID;

    // warp/frag mapping
    const int wid = tid >> 5, lane = tid & 31;
    const int wm = wid >> 1, wn = wid & 1;
    const int gp = lane >> 2, tg = lane & 3;

    float acc[2][10][4] = {};
    float rA[16];

    // --- helpers as lambdas ---
    auto loadA = [&](int kb) {
        const int k0 = kb * CBK;
#pragma unroll
        for (int v = 0; v < 4; v++) {
            int kg = k0 + ak0 + v * 4;
            float4 av, hv;
            if (kg < HID) {
                av = *(const float4*)(ap + kg);
                hv = *(const float4*)(hp + kg);
            } else {
                av = make_float4(0.f, 0.f, 0.f, 0.f);
                hv = av;
            }
            rA[v * 4 + 0] = av.x - hv.x; rA[v * 4 + 1] = av.y - hv.y;
            rA[v * 4 + 2] = av.z - hv.z; rA[v * 4 + 3] = av.w - hv.w;
        }
    };

    auto stsA = [&](int st) {
        uint16_t* Ah = smem + st * ST_HALFS;
        uint16_t* Al = Ah + OFF_AL;
#pragma unroll
        for (int v = 0; v < 4; v++) {
#pragma unroll
            for (int j = 0; j < 4; j += 2) {
                float v0 = rA[v * 4 + j], v1 = rA[v * 4 + j + 1];
                uint16_t h0b = f2bf_bits(v0);
                uint16_t l0b = f2bf_bits(v0 - bf_bits2f(h0b));
                uint16_t h1b = f2bf_bits(v1);
                uint16_t l1b = f2bf_bits(v1 - bf_bits2f(h1b));
                int kc = ai * ASTR + ak0 + v * 4 + j;
                *(uint32_t*)&Ah[kc] = (uint32_t)h0b | ((uint32_t)h1b << 16);
                *(uint32_t*)&Al[kc] = (uint32_t)l0b | ((uint32_t)l1b << 16);
            }
        }
    };

    auto cpB = [&](int kb, int st) {
        const int k0 = kb * CBK;
#pragma unroll
        for (int q = 0; q < 5; q++) {
            int idx = tid + 256 * q;          // 0..1279
            int hl = idx >= 640;
            int r = idx - (hl ? 640 : 0);     // 0..639
            int n = r >> 2;
            int c = (r & 3) << 3;             // halfs: 0,8,16,24
            const uint16_t* src = (hl ? WloT : WhiT) +
                                  (size_t)(jb + n) * KPAD + k0 + c;
            uint32_t dst = smem_u32 +
                (uint32_t)(st * ST_HALFS + (hl ? OFF_BL : OFF_BH) + n * ASTR + c) * 2u;
            cp16(dst, src);
        }
    };

    // ---- prologue: fill stage 0 ----
    loadA(0);
    cpB(0, 0);
    cp_commit();
    stsA(0);
    cp_wait0();
    __syncthreads();

    for (int kb = 0; kb < NKB; kb++) {
        const int cur = kb & 1;
        const int nxt = cur ^ 1;
        if (kb + 1 < NKB) {
            loadA(kb + 1);
            cpB(kb + 1, nxt);
            cp_commit();
        }

        // ---- compute on stage cur ----
        const uint16_t* Ah = smem + cur * ST_HALFS;
        const uint16_t* Al = Ah + OFF_AL;
        const uint16_t* Bh = Ah + OFF_BH;
        const uint16_t* Bl = Ah + OFF_BL;
#pragma unroll
        for (int kk = 0; kk < CBK; kk += 16) {
            uint32_t ah[2][4], al[2][4];
#pragma unroll
            for (int f = 0; f < 2; f++) {
                int r0 = (wm * 32 + f * 16 + gp) * ASTR;
                int c0 = kk + tg * 2;
                ah[f][0] = *(const uint32_t*)&Ah[r0 + c0];
                ah[f][1] = *(const uint32_t*)&Ah[r0 + 8 * ASTR + c0];
                ah[f][2] = *(const uint32_t*)&Ah[r0 + c0 + 8];
                ah[f][3] = *(const uint32_t*)&Ah[r0 + 8 * ASTR + c0 + 8];
                al[f][0] = *(const uint32_t*)&Al[r0 + c0];
                al[f][1] = *(const uint32_t*)&Al[r0 + 8 * ASTR + c0];
                al[f][2] = *(const uint32_t*)&Al[r0 + c0 + 8];
                al[f][3] = *(const uint32_t*)&Al[r0 + 8 * ASTR + c0 + 8];
            }
#pragma unroll
            for (int j = 0; j < 10; j++) {
                int n0 = (wn * 80 + j * 8 + gp) * ASTR;
                int ck = kk + tg * 2;
                uint32_t bh0 = *(const uint32_t*)&Bh[n0 + ck];
                uint32_t bh1 = *(const uint32_t*)&Bh[n0 + ck + 8];
                uint32_t bl0 = *(const uint32_t*)&Bl[n0 + ck];
                uint32_t bl1 = *(const uint32_t*)&Bl[n0 + ck + 8];
#pragma unroll
                for (int f = 0; f < 2; f++) {
                    mma_bf16(acc[f][j], ah[f], bh0, bh1);
                    mma_bf16(acc[f][j], ah[f], bl0, bl1);
                    mma_bf16(acc[f][j], al[f], bh0, bh1);
                }
            }
        }

        if (kb + 1 < NKB) {
            stsA(nxt);
            cp_wait0();
        }
        __syncthreads();
    }

    // ---- epilogue: + bias + h0 skip, relu, store ----
#pragma unroll
    for (int f = 0; f < 2; f++) {
#pragma unroll
        for (int j = 0; j < 10; j++) {
            int n0 = jb + wn * 80 + j * 8 + tg * 2;
            if (n0 >= HID) continue;
            float2 bb = *(const float2*)(bias + n0);
#pragma unroll
            for (int half = 0; half < 2; half++) {
                int e = eb + wm * 32 + f * 16 + gp + half * 8;
                float2 hz = *(const float2*)(h0 + (size_t)e * HID + n0);
                float o0 = acc[f][j][half * 2 + 0] + bb.x + hz.x;
                float o1 = acc[f][j][half * 2 + 1] + bb.y + hz.y;
                float2 o = make_float2(fmaxf(o0, 0.f), fmaxf(o1, 0.f));
                *(float2*)(out + (size_t)e * HID + n0) = o;
            }
        }
    }
}

// ---------------- SIMT GEMMs (init, e2n) ----------------

// h0[e] = relu(cat(x[row[e]], edge_attr[e]) @ W_init + b)   K = 80
__global__ void __launch_bounds__(256, 4) k_init(
    const float* __restrict__ x, const float* __restrict__ ea,
    const float* __restrict__ W, const float* __restrict__ bias,
    const int* __restrict__ row, float* __restrict__ out)
{
    __shared__ float As[TM][TK + 1];
    __shared__ float Bs[TK][TN];
    const int eb = blockIdx.y * TM;
    const int jb = blockIdx.x * TN;
    const int tid = threadIdx.x;

    const int lm = tid >> 2;
    const int lk = (tid & 3) << 2;
    const int e_l = eb + lm;
    const float* xp = x  + (size_t)__ldg(row + e_l) * FN;
    const float* ep = ea + (size_t)e_l * FE;

    const int bk = tid >> 4;
    const int bj = (tid & 15) << 2;
    const bool bj_ok = (jb + bj) < HID;

    const int tm = (tid >> 4) << 2;
    const int tn = (tid & 15) << 2;

    float acc[4][4] = {};

    for (int k0 = 0; k0 < FN + FE; k0 += TK) {
        int ka = k0 + lk;
        float4 av = (ka < FN) ? *(const float4*)(xp + ka)
                              : *(const float4*)(ep + (ka - FN));
        As[lm][lk + 0] = av.x; As[lm][lk + 1] = av.y;
        As[lm][lk + 2] = av.z; As[lm][lk + 3] = av.w;

        int kb = k0 + bk;
        float4 wv = make_float4(0.f, 0.f, 0.f, 0.f);
        if (bj_ok) wv = *(const float4*)(W + (size_t)kb * HID + jb + bj);
        *(float4*)&Bs[bk][bj] = wv;

        __syncthreads();
#pragma unroll
        for (int k = 0; k < TK; k++) {
            float4 bv = *(const float4*)&Bs[k][tn];
            float a0 = As[tm + 0][k], a1 = As[tm + 1][k];
            float a2 = As[tm + 2][k], a3 = As[tm + 3][k];
            acc[0][0] += a0 * bv.x; acc[0][1] += a0 * bv.y; acc[0][2] += a0 * bv.z; acc[0][3] += a0 * bv.w;
            acc[1][0] += a1 * bv.x; acc[1][1] += a1 * bv.y; acc[1][2] += a1 * bv.z; acc[1][3] += a1 * bv.w;
            acc[2][0] += a2 * bv.x; acc[2][1] += a2 * bv.y; acc[2][2] += a2 * bv.z; acc[2][3] += a2 * bv.w;
            acc[3][0] += a3 * bv.x; acc[3][1] += a3 * bv.y; acc[3][2] += a3 * bv.z; acc[3][3] += a3 * bv.w;
        }
        __syncthreads();
    }

    const int j = jb + tn;
    if (j < HID) {
        float4 bb = *(const float4*)(bias + j);
#pragma unroll
        for (int i = 0; i < 4; i++) {
            int e = eb + tm + i;
            float4 o;
            o.x = fmaxf(acc[i][0] + bb.x, 0.f);
            o.y = fmaxf(acc[i][1] + bb.y, 0.f);
            o.z = fmaxf(acc[i][2] + bb.z, 0.f);
            o.w = fmaxf(acc[i][3] + bb.w, 0.f);
            *(float4*)(out + (size_t)e * HID + j) = o;
        }
    }
}

// hn[n] = relu(cat(x[n], s[n]) @ W_e2n + b)   K = 364
__global__ void __launch_bounds__(256, 4) k_e2n(
    const float* __restrict__ x, const float* __restrict__ s,
    const float* __restrict__ W, const float* __restrict__ bias,
    float* __restrict__ out)
{
    __shared__ float As[TM][TK + 1];
    __shared__ float Bs[TK][TN];
    const int nb = blockIdx.y * TM;
    const int jb = blockIdx.x * TN;
    const int tid = threadIdx.x;
    const int KT = FN + HID;

    const int lm = tid >> 2;
    const int lk = (tid & 3) << 2;
    const int n_l = nb + lm;
    const int n_c = n_l < NN ? n_l : NN - 1;
    const float* xp = x + (size_t)n_c * FN;
    const float* sp = s + (size_t)n_c * HID;

    const int bk = tid >> 4;
    const int bj = (tid & 15) << 2;
    const bool bj_ok = (jb + bj) < HID;

    const int tm = (tid >> 4) << 2;
    const int tn = (tid & 15) << 2;

    float acc[4][4] = {};

    for (int k0 = 0; k0 < KT; k0 += TK) {
        int ka = k0 + lk;
        float4 av = make_float4(0.f, 0.f, 0.f, 0.f);
        if (ka < FN)      av = *(const float4*)(xp + ka);
        else if (ka < KT) av = *(const float4*)(sp + (ka - FN));
        As[lm][lk + 0] = av.x; As[lm][lk + 1] = av.y;
        As[lm][lk + 2] = av.z; As[lm][lk + 3] = av.w;

        int kb = k0 + bk;
        float4 wv = make_float4(0.f, 0.f, 0.f, 0.f);
        if (kb < KT && bj_ok) wv = *(const float4*)(W + (size_t)kb * HID + jb + bj);
        *(float4*)&Bs[bk][bj] = wv;

        __syncthreads();
#pragma unroll
        for (int k = 0; k < TK; k++) {
            float4 bv = *(const float4*)&Bs[k][tn];
            float a0 = As[tm + 0][k], a1 = As[tm + 1][k];
            float a2 = As[tm + 2][k], a3 = As[tm + 3][k];
            acc[0][0] += a0 * bv.x; acc[0][1] += a0 * bv.y; acc[0][2] += a0 * bv.z; acc[0][3] += a0 * bv.w;
            acc[1][0] += a1 * bv.x; acc[1][1] += a1 * bv.y; acc[1][2] += a1 * bv.z; acc[1][3] += a1 * bv.w;
            acc[2][0] += a2 * bv.x; acc[2][1] += a2 * bv.y; acc[2][2] += a2 * bv.z; acc[2][3] += a2 * bv.w;
            acc[3][0] += a3 * bv.x; acc[3][1] += a3 * bv.y; acc[3][2] += a3 * bv.z; acc[3][3] += a3 * bv.w;
        }
        __syncthreads();
    }

    const int j = jb + tn;
    if (j < HID) {
        float4 bb = *(const float4*)(bias + j);
#pragma unroll
        for (int i = 0; i < 4; i++) {
            int n = nb + tm + i;
            if (n >= NN) break;
            float4 o;
            o.x = fmaxf(acc[i][0] + bb.x, 0.f);
            o.y = fmaxf(acc[i][1] + bb.y, 0.f);
            o.z = fmaxf(acc[i][2] + bb.z, 0.f);
            o.w = fmaxf(acc[i][3] + bb.w, 0.f);
            *(float4*)(out + (size_t)n * HID + j) = o;
        }
    }
}

// ---------------- launch ----------------
extern "C" void kernel_launch(void* const* d_in, const int* in_sizes, int n_in,
                              void* d_out, int out_size) {
    const float* x        = (const float*)d_in[0];
    const float* edge_attr= (const float*)d_in[1];
    const int*   edge_idx = (const int*)  d_in[2];
    const int*   batch    = (const int*)  d_in[3];
    const float* W_init   = (const float*)d_in[4];
    const float* b_init   = (const float*)d_in[5];
    const float* W_convs  = (const float*)d_in[6];
    const float* b_convs  = (const float*)d_in[7];
    const float* W_e2n    = (const float*)d_in[8];
    const float* b_e2n    = (const float*)d_in[9];
    const float* W_ffn    = (const float*)d_in[10];
    const float* b_ffn    = (const float*)d_in[11];
    float* out = (float*)d_out;

    const int* row = edge_idx;
    const int* col = edge_idx + NE;

    float *h0, *hA, *hB, *a, *hn, *pool;
    uint16_t *WhiT, *WloT;
    cudaGetSymbolAddress((void**)&h0,   g_h0);
    cudaGetSymbolAddress((void**)&hA,   g_hA);
    cudaGetSymbolAddress((void**)&hB,   g_hB);
    cudaGetSymbolAddress((void**)&a,    g_a);
    cudaGetSymbolAddress((void**)&hn,   g_hn);
    cudaGetSymbolAddress((void**)&pool, g_pool);
    cudaGetSymbolAddress((void**)&WhiT, g_WhiT);
    cudaGetSymbolAddress((void**)&WloT, g_WloT);

    cudaFuncSetAttribute(k_conv_mma, cudaFuncAttributeMaxDynamicSharedMemorySize,
                         SMEM_BYTES);

    const int a4 = NN * (HID / 4);
    const int e4 = NE * (HID / 4);
    const int p4 = NG * (HID / 4);

    // split conv weights (bf16 hi/lo, transposed [n][k], padded to 320x320)
    const int wtot = NDEPTH * NPR * KPAD;
    k_splitW<<<(wtot + 255) / 256, 256>>>(W_convs, WhiT, WloT);

    // h0 = relu(edge_init(cat(x[row], edge_attr)))
    const dim3 init_grid((HID + TN - 1) / TN, NE / TM);
    k_init<<<init_grid, 256>>>(x, edge_attr, W_init, b_init, row, h0);

    const dim3 conv_grid(2, NE / CBM);  // (2, 2500)
    const float* hcur = h0;
    float* bufs[2] = {hA, hB};
    for (int l = 0; l < NDEPTH; l++) {
        k_zero<<<(a4 + 255) / 256, 256>>>((float4*)a, a4);
        k_scatter_edges<<<(e4 + 255) / 256, 256>>>((const float4*)hcur, col, a);
        float* hnext = bufs[l & 1];
        k_conv_mma<<<conv_grid, 256, SMEM_BYTES>>>(a, hcur, h0,
                                       WhiT + (size_t)l * NPR * KPAD,
                                       WloT + (size_t)l * NPR * KPAD,
                                       b_convs + (size_t)l * HID, row, hnext);
        hcur = hnext;
    }

    // final segment sum -> s (reuse a), node MLP, pooling, FFN
    k_zero<<<(a4 + 255) / 256, 256>>>((float4*)a, a4);
    k_scatter_edges<<<(e4 + 255) / 256, 256>>>((const float4*)hcur, col, a);

    const dim3 e2n_grid((HID + TN - 1) / TN, (NN + TM - 1) / TM);
    k_e2n<<<e2n_grid, 256>>>(x, a, W_e2n, b_e2n, hn);

    k_zero<<<(p4 + 255) / 256, 256>>>((float4*)pool, p4);
    k_scatter_pool<<<(a4 + 255) / 256, 256>>>((const float4*)hn, batch, pool);
    k_ffn<<<NG, 128>>>(pool, W_ffn, b_ffn, out);
}

// round 8
// speedup vs baseline: 1.3053x; 1.3053x over previous
#include <cuda_runtime.h>
#include <cuda_bf16.h>
#include <cstdint>

#define NN 20000
#define NE 320000
#define FN 64
#define FE 16
#define HID 300
#define NDEPTH 3
#define NG 128

// SIMT GEMM tiles (init / e2n)
#define TM 64
#define TN 64
#define TK 16

// conv MMA tiles
#define CBM 128
#define CBN 160
#define CBK 32
#define KPAD 320
#define NPR 320            // W rows padded (HID=300 -> 320)
#define NKB (KPAD / CBK)   // 10
#define ASTR 40            // padded k-stride in halfs

// ---------------- static scratch (no runtime allocation allowed) ----------------
__device__ __align__(256) float g_h0[(size_t)NE * HID];
__device__ __align__(256) float g_hA[(size_t)NE * HID];
__device__ __align__(256) float g_hB[(size_t)NE * HID];
__device__ __align__(256) float g_a [(size_t)NN * HID];
__device__ __align__(256) float g_hn[(size_t)NN * HID];
__device__ __align__(256) float g_pool[(size_t)NG * HID];
__device__ __align__(256) uint16_t g_WhiT[(size_t)NDEPTH * NPR * KPAD];
__device__ __align__(256) uint16_t g_WloT[(size_t)NDEPTH * NPR * KPAD];

// ---------------- helpers ----------------
__device__ __forceinline__ uint16_t f2bf_bits(float v) {
    __nv_bfloat16 b = __float2bfloat16(v);
    return *reinterpret_cast<uint16_t*>(&b);
}
__device__ __forceinline__ float bf_bits2f(uint16_t u) {
    __nv_bfloat16 b = *reinterpret_cast<__nv_bfloat16*>(&u);
    return __bfloat162float(b);
}

__device__ __forceinline__ void mma_bf16(float* d, const uint32_t* a,
                                         uint32_t b0, uint32_t b1) {
    asm volatile(
        "mma.sync.aligned.m16n8k16.row.col.f32.bf16.bf16.f32 "
        "{%0,%1,%2,%3}, {%4,%5,%6,%7}, {%8,%9}, {%0,%1,%2,%3};"
        : "+f"(d[0]), "+f"(d[1]), "+f"(d[2]), "+f"(d[3])
        : "r"(a[0]), "r"(a[1]), "r"(a[2]), "r"(a[3]), "r"(b0), "r"(b1));
}

__device__ __forceinline__ void ldsm4(uint32_t* r, uint32_t addr) {
    asm volatile("ldmatrix.sync.aligned.m8n8.x4.shared.b16 {%0,%1,%2,%3}, [%4];"
                 : "=r"(r[0]), "=r"(r[1]), "=r"(r[2]), "=r"(r[3]) : "r"(addr));
}
__device__ __forceinline__ void ldsm2(uint32_t* r, uint32_t addr) {
    asm volatile("ldmatrix.sync.aligned.m8n8.x2.shared.b16 {%0,%1}, [%2];"
                 : "=r"(r[0]), "=r"(r[1]) : "r"(addr));
}

__device__ __forceinline__ void red_v4(float* dst, float4 v) {
    asm volatile("red.global.add.v4.f32 [%0], {%1,%2,%3,%4};" ::
                 "l"(dst), "f"(v.x), "f"(v.y), "f"(v.z), "f"(v.w) : "memory");
}

// ---------------- utility kernels ----------------
__global__ void k_zero(float4* p, int n4) {
    int i = blockIdx.x * blockDim.x + threadIdx.x;
    if (i < n4) p[i] = make_float4(0.f, 0.f, 0.f, 0.f);
}

// split W_convs into transposed, padded bf16 hi/lo: W_T[l][n][k], n padded to 320
__global__ void k_splitW(const float* __restrict__ W,
                         uint16_t* __restrict__ WhiT, uint16_t* __restrict__ WloT) {
    int idx = blockIdx.x * blockDim.x + threadIdx.x;
    const int total = NDEPTH * NPR * KPAD;
    if (idx >= total) return;
    int l = idx / (NPR * KPAD);
    int rem = idx - l * (NPR * KPAD);
    int n = rem / KPAD;
    int k = rem - n * KPAD;
    float v = (k < HID && n < HID) ? W[(size_t)l * HID * HID + (size_t)k * HID + n] : 0.f;
    uint16_t hb = f2bf_bits(v);
    float lo = v - bf_bits2f(hb);
    WhiT[idx] = hb;
    WloT[idx] = f2bf_bits(lo);
}

// segment_sum over edges: a[col[e]] += h[e]
__global__ void k_scatter_edges(const float4* __restrict__ h4,
                                const int* __restrict__ col,
                                float* __restrict__ a) {
    int t = blockIdx.x * blockDim.x + threadIdx.x;
    const int total = NE * (HID / 4);
    if (t >= total) return;
    int e = t / (HID / 4);
    int c = t - e * (HID / 4);
    float4 v = h4[t];
    float* dst = a + (size_t)__ldg(col + e) * HID + (c << 2);
    red_v4(dst, v);
}

// pooled[batch[n]] += hn[n]
__global__ void k_scatter_pool(const float4* __restrict__ hn4,
                               const int* __restrict__ batch,
                               float* __restrict__ pool) {
    int t = blockIdx.x * blockDim.x + threadIdx.x;
    const int total = NN * (HID / 4);
    if (t >= total) return;
    int n = t / (HID / 4);
    int c = t - n * (HID / 4);
    float4 v = hn4[t];
    float* dst = pool + (size_t)__ldg(batch + n) * HID + (c << 2);
    red_v4(dst, v);
}

__global__ void k_ffn(const float* __restrict__ pool, const float* __restrict__ W,
                      const float* __restrict__ b, float* __restrict__ out) {
    __shared__ float red[128];
    int g = blockIdx.x;
    float s = 0.f;
    for (int j = threadIdx.x; j < HID; j += 128)
        s += pool[(size_t)g * HID + j] * W[j];
    red[threadIdx.x] = s;
    __syncthreads();
    for (int k = 64; k > 0; k >>= 1) {
        if (threadIdx.x < k) red[threadIdx.x] += red[threadIdx.x + k];
        __syncthreads();
    }
    if (threadIdx.x == 0) out[g] = red[0] + b[0];
}

// ---------------- conv layer via tensor cores (split-bf16, 3-MMA) ----------------
// out[e] = relu((a[row[e]] - h[e^1]) @ W + b + h0[e])
// 512 threads / 16 warps (4x4), single-buffer smem, reg prefetch, ldmatrix frags.
__global__ void __launch_bounds__(512, 1) k_conv_mma(
    const float* __restrict__ a, const float* __restrict__ h,
    const float* __restrict__ h0, const uint16_t* __restrict__ WhiT,
    const uint16_t* __restrict__ WloT, const float* __restrict__ bias,
    const int* __restrict__ row, float* __restrict__ out)
{
    __shared__ uint16_t Ah[CBM * ASTR];
    __shared__ uint16_t Al[CBM * ASTR];
    __shared__ uint16_t Bh[CBN * ASTR];
    __shared__ uint16_t Bl[CBN * ASTR];
    __shared__ int rows_s[CBM];

    const int tid = threadIdx.x;
    const int eb = blockIdx.y * CBM;
    const int jb = blockIdx.x * CBN;

    if (tid < CBM) rows_s[tid] = __ldg(row + eb + tid);
    __syncthreads();

    // A staging: thread covers row ai, 8 consecutive k at ak0
    const int ai = tid >> 2;
    const int ak0 = (tid & 3) << 3;
    const float* ap = a + (size_t)rows_s[ai] * HID;
    const float* hp = h + (size_t)((eb + ai) ^ 1) * HID;

    // warp/frag mapping: 16 warps = wm(4) x wn(4); warp tile 32(M) x 40(N)
    const int wid = tid >> 5, lane = tid & 31;
    const int wm = wid >> 2, wn = wid & 3;
    const int gp = lane >> 2, tg = lane & 3;

    float acc[2][5][4] = {};
    float rA[8];
    uint32_t rBh[5], rBl[5];

    // ldmatrix base offsets (in halfs, kk added later)
    const int lg = lane >> 3;        // ldmatrix address group 0..3
    const int l7 = lane & 7;
    // A (x4, per f): row = wm*32 + f*16 + l7 + (lg&1)*8, col = (lg>>1)*8
    int a_base0 = (wm * 32 + 0  + l7 + (lg & 1) * 8) * ASTR + (lg >> 1) * 8;
    int a_base1 = (wm * 32 + 16 + l7 + (lg & 1) * 8) * ASTR + (lg >> 1) * 8;
    // B (x4, j-pair jp): row = wn*40 + (jp*2 + (lg>>1))*8 + l7, col = (lg&1)*8
    int b_base0 = (wn * 40 + (0 + (lg >> 1)) * 8 + l7) * ASTR + (lg & 1) * 8;
    int b_base1 = (wn * 40 + (2 + (lg >> 1)) * 8 + l7) * ASTR + (lg & 1) * 8;
    // B (x2, j=4): lanes 0-15, row = wn*40+32+l7, col = ((lane>>3)&1)*8
    int b_base2 = (wn * 40 + 32 + l7) * ASTR + (lg & 1) * 8;

    const uint32_t ahS = (uint32_t)__cvta_generic_to_shared(Ah);
    const uint32_t alS = (uint32_t)__cvta_generic_to_shared(Al);
    const uint32_t bhS = (uint32_t)__cvta_generic_to_shared(Bh);
    const uint32_t blS = (uint32_t)__cvta_generic_to_shared(Bl);

    auto loadA = [&](int kb) {
        const int k0 = kb * CBK;
#pragma unroll
        for (int v = 0; v < 2; v++) {
            int kg = k0 + ak0 + v * 4;
            float4 av, hv;
            if (kg < HID) {
                av = *(const float4*)(ap + kg);
                hv = *(const float4*)(hp + kg);
            } else {
                av = make_float4(0.f, 0.f, 0.f, 0.f);
                hv = av;
            }
            rA[v * 4 + 0] = av.x - hv.x; rA[v * 4 + 1] = av.y - hv.y;
            rA[v * 4 + 2] = av.z - hv.z; rA[v * 4 + 3] = av.w - hv.w;
        }
    };

    auto loadB = [&](int kb) {
        const int k0 = kb * CBK;
#pragma unroll
        for (int q = 0; q < 5; q++) {
            int idx = tid + 512 * q;       // 0..2559
            int n = idx >> 4, kw = idx & 15;
            const uint16_t* s1 = WhiT + (size_t)(jb + n) * KPAD + k0 + kw * 2;
            const uint16_t* s2 = WloT + (size_t)(jb + n) * KPAD + k0 + kw * 2;
            rBh[q] = *(const uint32_t*)s1;
            rBl[q] = *(const uint32_t*)s2;
        }
    };

    auto stsAB = [&]() {
#pragma unroll
        for (int j = 0; j < 8; j += 2) {
            float v0 = rA[j], v1 = rA[j + 1];
            uint16_t h0b = f2bf_bits(v0);
            uint16_t l0b = f2bf_bits(v0 - bf_bits2f(h0b));
            uint16_t h1b = f2bf_bits(v1);
            uint16_t l1b = f2bf_bits(v1 - bf_bits2f(h1b));
            int kc = ai * ASTR + ak0 + j;
            *(uint32_t*)&Ah[kc] = (uint32_t)h0b | ((uint32_t)h1b << 16);
            *(uint32_t*)&Al[kc] = (uint32_t)l0b | ((uint32_t)l1b << 16);
        }
#pragma unroll
        for (int q = 0; q < 5; q++) {
            int idx = tid + 512 * q;
            int n = idx >> 4, kw = idx & 15;
            *(uint32_t*)&Bh[n * ASTR + kw * 2] = rBh[q];
            *(uint32_t*)&Bl[n * ASTR + kw * 2] = rBl[q];
        }
    };

    // ---- prologue ----
    loadA(0);
    loadB(0);

    for (int kb = 0; kb < NKB; kb++) {
        stsAB();
        __syncthreads();

        if (kb + 1 < NKB) {
            loadA(kb + 1);
            loadB(kb + 1);
        }

        // ---- compute on smem tile kb ----
#pragma unroll
        for (int kk = 0; kk < CBK; kk += 16) {
            uint32_t bhf[5][2], blf[5][2], t4[4];
            // B fragments: 2x ldsm4 + 1x ldsm2, for hi and lo
            ldsm4(t4, bhS + (uint32_t)(b_base0 + kk) * 2u);
            bhf[0][0] = t4[0]; bhf[0][1] = t4[1]; bhf[1][0] = t4[2]; bhf[1][1] = t4[3];
            ldsm4(t4, bhS + (uint32_t)(b_base1 + kk) * 2u);
            bhf[2][0] = t4[0]; bhf[2][1] = t4[1]; bhf[3][0] = t4[2]; bhf[3][1] = t4[3];
            ldsm2(bhf[4], bhS + (uint32_t)(b_base2 + kk) * 2u);
            ldsm4(t4, blS + (uint32_t)(b_base0 + kk) * 2u);
            blf[0][0] = t4[0]; blf[0][1] = t4[1]; blf[1][0] = t4[2]; blf[1][1] = t4[3];
            ldsm4(t4, blS + (uint32_t)(b_base1 + kk) * 2u);
            blf[2][0] = t4[0]; blf[2][1] = t4[1]; blf[3][0] = t4[2]; blf[3][1] = t4[3];
            ldsm2(blf[4], blS + (uint32_t)(b_base2 + kk) * 2u);

#pragma unroll
            for (int f = 0; f < 2; f++) {
                uint32_t ah[4], al[4];
                int ab = (f == 0 ? a_base0 : a_base1) + kk;
                ldsm4(ah, ahS + (uint32_t)ab * 2u);
                ldsm4(al, alS + (uint32_t)ab * 2u);
#pragma unroll
                for (int j = 0; j < 5; j++) {
                    mma_bf16(acc[f][j], ah, bhf[j][0], bhf[j][1]);
                    mma_bf16(acc[f][j], ah, blf[j][0], blf[j][1]);
                    mma_bf16(acc[f][j], al, bhf[j][0], bhf[j][1]);
                }
            }
        }
        __syncthreads();
    }

    // ---- epilogue: + bias + h0 skip, relu, store ----
#pragma unroll
    for (int f = 0; f < 2; f++) {
#pragma unroll
        for (int j = 0; j < 5; j++) {
            int n0 = jb + wn * 40 + j * 8 + tg * 2;
            if (n0 >= HID) continue;
            float2 bb = *(const float2*)(bias + n0);
#pragma unroll
            for (int half = 0; half < 2; half++) {
                int e = eb + wm * 32 + f * 16 + gp + half * 8;
                float2 hz = *(const float2*)(h0 + (size_t)e * HID + n0);
                float o0 = acc[f][j][half * 2 + 0] + bb.x + hz.x;
                float o1 = acc[f][j][half * 2 + 1] + bb.y + hz.y;
                float2 o = make_float2(fmaxf(o0, 0.f), fmaxf(o1, 0.f));
                *(float2*)(out + (size_t)e * HID + n0) = o;
            }
        }
    }
}

// ---------------- SIMT GEMMs (init, e2n) ----------------

// h0[e] = relu(cat(x[row[e]], edge_attr[e]) @ W_init + b)   K = 80
__global__ void __launch_bounds__(256, 4) k_init(
    const float* __restrict__ x, const float* __restrict__ ea,
    const float* __restrict__ W, const float* __restrict__ bias,
    const int* __restrict__ row, float* __restrict__ out)
{
    __shared__ float As[TM][TK + 1];
    __shared__ float Bs[TK][TN];
    const int eb = blockIdx.y * TM;
    const int jb = blockIdx.x * TN;
    const int tid = threadIdx.x;

    const int lm = tid >> 2;
    const int lk = (tid & 3) << 2;
    const int e_l = eb + lm;
    const float* xp = x  + (size_t)__ldg(row + e_l) * FN;
    const float* ep = ea + (size_t)e_l * FE;

    const int bk = tid >> 4;
    const int bj = (tid & 15) << 2;
    const bool bj_ok = (jb + bj) < HID;

    const int tm = (tid >> 4) << 2;
    const int tn = (tid & 15) << 2;

    float acc[4][4] = {};

    for (int k0 = 0; k0 < FN + FE; k0 += TK) {
        int ka = k0 + lk;
        float4 av = (ka < FN) ? *(const float4*)(xp + ka)
                              : *(const float4*)(ep + (ka - FN));
        As[lm][lk + 0] = av.x; As[lm][lk + 1] = av.y;
        As[lm][lk + 2] = av.z; As[lm][lk + 3] = av.w;

        int kb = k0 + bk;
        float4 wv = make_float4(0.f, 0.f, 0.f, 0.f);
        if (bj_ok) wv = *(const float4*)(W + (size_t)kb * HID + jb + bj);
        *(float4*)&Bs[bk][bj] = wv;

        __syncthreads();
#pragma unroll
        for (int k = 0; k < TK; k++) {
            float4 bv = *(const float4*)&Bs[k][tn];
            float a0 = As[tm + 0][k], a1 = As[tm + 1][k];
            float a2 = As[tm + 2][k], a3 = As[tm + 3][k];
            acc[0][0] += a0 * bv.x; acc[0][1] += a0 * bv.y; acc[0][2] += a0 * bv.z; acc[0][3] += a0 * bv.w;
            acc[1][0] += a1 * bv.x; acc[1][1] += a1 * bv.y; acc[1][2] += a1 * bv.z; acc[1][3] += a1 * bv.w;
            acc[2][0] += a2 * bv.x; acc[2][1] += a2 * bv.y; acc[2][2] += a2 * bv.z; acc[2][3] += a2 * bv.w;
            acc[3][0] += a3 * bv.x; acc[3][1] += a3 * bv.y; acc[3][2] += a3 * bv.z; acc[3][3] += a3 * bv.w;
        }
        __syncthreads();
    }

    const int j = jb + tn;
    if (j < HID) {
        float4 bb = *(const float4*)(bias + j);
#pragma unroll
        for (int i = 0; i < 4; i++) {
            int e = eb + tm + i;
            float4 o;
            o.x = fmaxf(acc[i][0] + bb.x, 0.f);
            o.y = fmaxf(acc[i][1] + bb.y, 0.f);
            o.z = fmaxf(acc[i][2] + bb.z, 0.f);
            o.w = fmaxf(acc[i][3] + bb.w, 0.f);
            *(float4*)(out + (size_t)e * HID + j) = o;
        }
    }
}

// hn[n] = relu(cat(x[n], s[n]) @ W_e2n + b)   K = 364
__global__ void __launch_bounds__(256, 4) k_e2n(
    const float* __restrict__ x, const float* __restrict__ s,
    const float* __restrict__ W, const float* __restrict__ bias,
    float* __restrict__ out)
{
    __shared__ float As[TM][TK + 1];
    __shared__ float Bs[TK][TN];
    const int nb = blockIdx.y * TM;
    const int jb = blockIdx.x * TN;
    const int tid = threadIdx.x;
    const int KT = FN + HID;

    const int lm = tid >> 2;
    const int lk = (tid & 3) << 2;
    const int n_l = nb + lm;
    const int n_c = n_l < NN ? n_l : NN - 1;
    const float* xp = x + (size_t)n_c * FN;
    const float* sp = s + (size_t)n_c * HID;

    const int bk = tid >> 4;
    const int bj = (tid & 15) << 2;
    const bool bj_ok = (jb + bj) < HID;

    const int tm = (tid >> 4) << 2;
    const int tn = (tid & 15) << 2;

    float acc[4][4] = {};

    for (int k0 = 0; k0 < KT; k0 += TK) {
        int ka = k0 + lk;
        float4 av = make_float4(0.f, 0.f, 0.f, 0.f);
        if (ka < FN)      av = *(const float4*)(xp + ka);
        else if (ka < KT) av = *(const float4*)(sp + (ka - FN));
        As[lm][lk + 0] = av.x; As[lm][lk + 1] = av.y;
        As[lm][lk + 2] = av.z; As[lm][lk + 3] = av.w;

        int kb = k0 + bk;
        float4 wv = make_float4(0.f, 0.f, 0.f, 0.f);
        if (kb < KT && bj_ok) wv = *(const float4*)(W + (size_t)kb * HID + jb + bj);
        *(float4*)&Bs[bk][bj] = wv;

        __syncthreads();
#pragma unroll
        for (int k = 0; k < TK; k++) {
            float4 bv = *(const float4*)&Bs[k][tn];
            float a0 = As[tm + 0][k], a1 = As[tm + 1][k];
            float a2 = As[tm + 2][k], a3 = As[tm + 3][k];
            acc[0][0] += a0 * bv.x; acc[0][1] += a0 * bv.y; acc[0][2] += a0 * bv.z; acc[0][3] += a0 * bv.w;
            acc[1][0] += a1 * bv.x; acc[1][1] += a1 * bv.y; acc[1][2] += a1 * bv.z; acc[1][3] += a1 * bv.w;
            acc[2][0] += a2 * bv.x; acc[2][1] += a2 * bv.y; acc[2][2] += a2 * bv.z; acc[2][3] += a2 * bv.w;
            acc[3][0] += a3 * bv.x; acc[3][1] += a3 * bv.y; acc[3][2] += a3 * bv.z; acc[3][3] += a3 * bv.w;
        }
        __syncthreads();
    }

    const int j = jb + tn;
    if (j < HID) {
        float4 bb = *(const float4*)(bias + j);
#pragma unroll
        for (int i = 0; i < 4; i++) {
            int n = nb + tm + i;
            if (n >= NN) break;
            float4 o;
            o.x = fmaxf(acc[i][0] + bb.x, 0.f);
            o.y = fmaxf(acc[i][1] + bb.y, 0.f);
            o.z = fmaxf(acc[i][2] + bb.z, 0.f);
            o.w = fmaxf(acc[i][3] + bb.w, 0.f);
            *(float4*)(out + (size_t)n * HID + j) = o;
        }
    }
}

// ---------------- launch ----------------
extern "C" void kernel_launch(void* const* d_in, const int* in_sizes, int n_in,
                              void* d_out, int out_size) {
    const float* x        = (const float*)d_in[0];
    const float* edge_attr= (const float*)d_in[1];
    const int*   edge_idx = (const int*)  d_in[2];
    const int*   batch    = (const int*)  d_in[3];
    const float* W_init   = (const float*)d_in[4];
    const float* b_init   = (const float*)d_in[5];
    const float* W_convs  = (const float*)d_in[6];
    const float* b_convs  = (const float*)d_in[7];
    const float* W_e2n    = (const float*)d_in[8];
    const float* b_e2n    = (const float*)d_in[9];
    const float* W_ffn    = (const float*)d_in[10];
    const float* b_ffn    = (const float*)d_in[11];
    float* out = (float*)d_out;

    const int* row = edge_idx;
    const int* col = edge_idx + NE;

    float *h0, *hA, *hB, *a, *hn, *pool;
    uint16_t *WhiT, *WloT;
    cudaGetSymbolAddress((void**)&h0,   g_h0);
    cudaGetSymbolAddress((void**)&hA,   g_hA);
    cudaGetSymbolAddress((void**)&hB,   g_hB);
    cudaGetSymbolAddress((void**)&a,    g_a);
    cudaGetSymbolAddress((void**)&hn,   g_hn);
    cudaGetSymbolAddress((void**)&pool, g_pool);
    cudaGetSymbolAddress((void**)&WhiT, g_WhiT);
    cudaGetSymbolAddress((void**)&WloT, g_WloT);

    const int a4 = NN * (HID / 4);
    const int e4 = NE * (HID / 4);
    const int p4 = NG * (HID / 4);

    // split conv weights (bf16 hi/lo, transposed [n][k], padded to 320x320)
    const int wtot = NDEPTH * NPR * KPAD;
    k_splitW<<<(wtot + 255) / 256, 256>>>(W_convs, WhiT, WloT);

    // h0 = relu(edge_init(cat(x[row], edge_attr)))
    const dim3 init_grid((HID + TN - 1) / TN, NE / TM);
    k_init<<<init_grid, 256>>>(x, edge_attr, W_init, b_init, row, h0);

    const dim3 conv_grid(2, NE / CBM);  // (2, 2500)
    const float* hcur = h0;
    float* bufs[2] = {hA, hB};
    for (int l = 0; l < NDEPTH; l++) {
        k_zero<<<(a4 + 255) / 256, 256>>>((float4*)a, a4);
        k_scatter_edges<<<(e4 + 255) / 256, 256>>>((const float4*)hcur, col, a);
        float* hnext = bufs[l & 1];
        k_conv_mma<<<conv_grid, 512>>>(a, hcur, h0,
                                       WhiT + (size_t)l * NPR * KPAD,
                                       WloT + (size_t)l * NPR * KPAD,
                                       b_convs + (size_t)l * HID, row, hnext);
        hcur = hnext;
    }

    // final segment sum -> s (reuse a), node MLP, pooling, FFN
    k_zero<<<(a4 + 255) / 256, 256>>>((float4*)a, a4);
    k_scatter_edges<<<(e4 + 255) / 256, 256>>>((const float4*)hcur, col, a);

    const dim3 e2n_grid((HID + TN - 1) / TN, (NN + TM - 1) / TM);
    k_e2n<<<e2n_grid, 256>>>(x, a, W_e2n, b_e2n, hn);

    k_zero<<<(p4 + 255) / 256, 256>>>((float4*)pool, p4);
    k_scatter_pool<<<(a4 + 255) / 256, 256>>>((const float4*)hn, batch, pool);
    k_ffn<<<NG, 128>>>(pool, W_ffn, b_ffn, out);
}

// round 12
// speedup vs baseline: 1.5037x; 1.1521x over previous
#include <cuda_runtime.h>
#include <cuda_bf16.h>
#include <cstdint>

#define NN 20000
#define NE 320000
#define FN 64
#define FE 16
#define HID 300
#define NDEPTH 3
#define NG 128

// SIMT GEMM tiles (init / e2n)
#define TM 64
#define TN 64
#define TK 16

// conv MMA tiles
#define CBM 128
#define CBN 160
#define CBK 32
#define KPAD 320
#define NPR 320            // W rows padded (HID=300 -> 320)
#define NKB (KPAD / CBK)   // 10
#define ASTR 40            // padded k-stride in halfs

// dynamic smem: 2 stages, per stage (halfs): Ah 5120 | Al 5120 | Bh 6400 | Bl 6400
#define ST_HALFS 23040
#define OFF_AL 5120
#define OFF_BH 10240
#define OFF_BL 16640
#define CONV_SMEM (2 * ST_HALFS * 2)   // 92160 bytes

// ---------------- static scratch (no runtime allocation allowed) ----------------
__device__ __align__(256) float g_h0[(size_t)NE * HID];
__device__ __align__(256) float g_hA[(size_t)NE * HID];
__device__ __align__(256) float g_hB[(size_t)NE * HID];
__device__ __align__(256) float g_a [(size_t)NN * HID];
__device__ __align__(256) float g_hn[(size_t)NN * HID];
__device__ __align__(256) float g_pool[(size_t)NG * HID];
__device__ __align__(256) uint16_t g_WhiT[(size_t)NDEPTH * NPR * KPAD];
__device__ __align__(256) uint16_t g_WloT[(size_t)NDEPTH * NPR * KPAD];

// ---------------- helpers ----------------
__device__ __forceinline__ uint16_t f2bf_bits(float v) {
    __nv_bfloat16 b = __float2bfloat16(v);
    return *reinterpret_cast<uint16_t*>(&b);
}
__device__ __forceinline__ float bf_bits2f(uint16_t u) {
    __nv_bfloat16 b = *reinterpret_cast<__nv_bfloat16*>(&u);
    return __bfloat162float(b);
}

__device__ __forceinline__ void mma_bf16(float* d, const uint32_t* a,
                                         uint32_t b0, uint32_t b1) {
    asm volatile(
        "mma.sync.aligned.m16n8k16.row.col.f32.bf16.bf16.f32 "
        "{%0,%1,%2,%3}, {%4,%5,%6,%7}, {%8,%9}, {%0,%1,%2,%3};"
        : "+f"(d[0]), "+f"(d[1]), "+f"(d[2]), "+f"(d[3])
        : "r"(a[0]), "r"(a[1]), "r"(a[2]), "r"(a[3]), "r"(b0), "r"(b1));
}

__device__ __forceinline__ void ldsm4(uint32_t* r, uint32_t addr) {
    asm volatile("ldmatrix.sync.aligned.m8n8.x4.shared.b16 {%0,%1,%2,%3}, [%4];"
                 : "=r"(r[0]), "=r"(r[1]), "=r"(r[2]), "=r"(r[3]) : "r"(addr));
}
__device__ __forceinline__ void ldsm2(uint32_t* r, uint32_t addr) {
    asm volatile("ldmatrix.sync.aligned.m8n8.x2.shared.b16 {%0,%1}, [%2];"
                 : "=r"(r[0]), "=r"(r[1]) : "r"(addr));
}

__device__ __forceinline__ void cp16(uint32_t dst, const void* src) {
    asm volatile("cp.async.cg.shared.global [%0], [%1], 16;" :: "r"(dst), "l"(src));
}
__device__ __forceinline__ void cp_commit() { asm volatile("cp.async.commit_group;"); }
__device__ __forceinline__ void cp_wait0()  { asm volatile("cp.async.wait_group 0;"); }

__device__ __forceinline__ void red_v4(float* dst, float4 v) {
    asm volatile("red.global.add.v4.f32 [%0], {%1,%2,%3,%4};" ::
                 "l"(dst), "f"(v.x), "f"(v.y), "f"(v.z), "f"(v.w) : "memory");
}

// ---------------- utility kernels ----------------
__global__ void k_zero(float4* p, int n4) {
    int i = blockIdx.x * blockDim.x + threadIdx.x;
    if (i < n4) p[i] = make_float4(0.f, 0.f, 0.f, 0.f);
}

// split W_convs into transposed, padded bf16 hi/lo: W_T[l][n][k], n padded to 320
__global__ void k_splitW(const float* __restrict__ W,
                         uint16_t* __restrict__ WhiT, uint16_t* __restrict__ WloT) {
    int idx = blockIdx.x * blockDim.x + threadIdx.x;
    const int total = NDEPTH * NPR * KPAD;
    if (idx >= total) return;
    int l = idx / (NPR * KPAD);
    int rem = idx - l * (NPR * KPAD);
    int n = rem / KPAD;
    int k = rem - n * KPAD;
    float v = (k < HID && n < HID) ? W[(size_t)l * HID * HID + (size_t)k * HID + n] : 0.f;
    uint16_t hb = f2bf_bits(v);
    float lo = v - bf_bits2f(hb);
    WhiT[idx] = hb;
    WloT[idx] = f2bf_bits(lo);
}

// segment_sum over edges: a[col[e]] += h[e]
__global__ void k_scatter_edges(const float4* __restrict__ h4,
                                const int* __restrict__ col,
                                float* __restrict__ a) {
    int t = blockIdx.x * blockDim.x + threadIdx.x;
    const int total = NE * (HID / 4);
    if (t >= total) return;
    int e = t / (HID / 4);
    int c = t - e * (HID / 4);
    float4 v = h4[t];
    float* dst = a + (size_t)__ldg(col + e) * HID + (c << 2);
    red_v4(dst, v);
}

// pooled[batch[n]] += hn[n]
__global__ void k_scatter_pool(const float4* __restrict__ hn4,
                               const int* __restrict__ batch,
                               float* __restrict__ pool) {
    int t = blockIdx.x * blockDim.x + threadIdx.x;
    const int total = NN * (HID / 4);
    if (t >= total) return;
    int n = t / (HID / 4);
    int c = t - n * (HID / 4);
    float4 v = hn4[t];
    float* dst = pool + (size_t)__ldg(batch + n) * HID + (c << 2);
    red_v4(dst, v);
}

__global__ void k_ffn(const float* __restrict__ pool, const float* __restrict__ W,
                      const float* __restrict__ b, float* __restrict__ out) {
    __shared__ float red[128];
    int g = blockIdx.x;
    float s = 0.f;
    for (int j = threadIdx.x; j < HID; j += 128)
        s += pool[(size_t)g * HID + j] * W[j];
    red[threadIdx.x] = s;
    __syncthreads();
    for (int k = 64; k > 0; k >>= 1) {
        if (threadIdx.x < k) red[threadIdx.x] += red[threadIdx.x + k];
        __syncthreads();
    }
    if (threadIdx.x == 0) out[g] = red[0] + b[0];
}

// ---------------- conv layer via tensor cores (split-bf16, 3-MMA) ----------------
// out[e] = relu((a[row[e]] - h[e^1]) @ W + b + h0[e])
// 512 threads / 16 warps (4x4), DOUBLE-buffered smem, cp.async B, ldmatrix frags.
__global__ void __launch_bounds__(512, 1) k_conv_mma(
    const float* __restrict__ a, const float* __restrict__ h,
    const float* __restrict__ h0, const uint16_t* __restrict__ WhiT,
    const uint16_t* __restrict__ WloT, const float* __restrict__ bias,
    const int* __restrict__ row, float* __restrict__ out)
{
    extern __shared__ __align__(256) uint16_t smem[];
    __shared__ int rows_s[CBM];

    const int tid = threadIdx.x;
    const int eb = blockIdx.y * CBM;
    const int jb = blockIdx.x * CBN;

    const uint32_t sbase = (uint32_t)__cvta_generic_to_shared(smem);

    if (tid < CBM) rows_s[tid] = __ldg(row + eb + tid);
    __syncthreads();

    // A staging: thread covers row ai, 8 consecutive k at ak0
    const int ai = tid >> 2;
    const int ak0 = (tid & 3) << 3;
    const float* ap = a + (size_t)rows_s[ai] * HID;
    const float* hp = h + (size_t)((eb + ai) ^ 1) * HID;

    // warp/frag mapping: 16 warps = wm(4) x wn(4); warp tile 32(M) x 40(N)
    const int wid = tid >> 5, lane = tid & 31;
    const int wm = wid >> 2, wn = wid & 3;
    const int gp = lane >> 2, tg = lane & 3;

    float acc[2][5][4] = {};
    float rA[8];

    // ldmatrix base offsets (halfs within a stage; kk + stage added later)
    const int lg = lane >> 3;
    const int l7 = lane & 7;
    int a_base0 = (wm * 32 + 0  + l7 + (lg & 1) * 8) * ASTR + (lg >> 1) * 8;
    int a_base1 = (wm * 32 + 16 + l7 + (lg & 1) * 8) * ASTR + (lg >> 1) * 8;
    int b_base0 = OFF_BH + (wn * 40 + (0 + (lg >> 1)) * 8 + l7) * ASTR + (lg & 1) * 8;
    int b_base1 = OFF_BH + (wn * 40 + (2 + (lg >> 1)) * 8 + l7) * ASTR + (lg & 1) * 8;
    int b_base2 = OFF_BH + (wn * 40 + 32 + l7) * ASTR + (lg & 1) * 8;
    const int dBL = OFF_BL - OFF_BH;   // hi->lo B delta
    const int dAL = OFF_AL;            // hi->lo A delta

    auto loadA = [&](int kb) {
        const int k0 = kb * CBK;
#pragma unroll
        for (int v = 0; v < 2; v++) {
            int kg = k0 + ak0 + v * 4;
            float4 av, hv;
            if (kg < HID) {
                av = *(const float4*)(ap + kg);
                hv = *(const float4*)(hp + kg);
            } else {
                av = make_float4(0.f, 0.f, 0.f, 0.f);
                hv = av;
            }
            rA[v * 4 + 0] = av.x - hv.x; rA[v * 4 + 1] = av.y - hv.y;
            rA[v * 4 + 2] = av.z - hv.z; rA[v * 4 + 3] = av.w - hv.w;
        }
    };

    auto stsA = [&](int st) {
        uint16_t* Ah = smem + st * ST_HALFS;
        uint32_t ph[4], pl[4];
#pragma unroll
        for (int j = 0; j < 8; j += 2) {
            float v0 = rA[j], v1 = rA[j + 1];
            uint16_t h0b = f2bf_bits(v0);
            uint16_t l0b = f2bf_bits(v0 - bf_bits2f(h0b));
            uint16_t h1b = f2bf_bits(v1);
            uint16_t l1b = f2bf_bits(v1 - bf_bits2f(h1b));
            ph[j >> 1] = (uint32_t)h0b | ((uint32_t)h1b << 16);
            pl[j >> 1] = (uint32_t)l0b | ((uint32_t)l1b << 16);
        }
        int kc = ai * ASTR + ak0;
        *(uint2*)&Ah[kc]           = make_uint2(ph[0], ph[1]);
        *(uint2*)&Ah[kc + 4]       = make_uint2(ph[2], ph[3]);
        *(uint2*)&Ah[dAL + kc]     = make_uint2(pl[0], pl[1]);
        *(uint2*)&Ah[dAL + kc + 4] = make_uint2(pl[2], pl[3]);
    };

    // B: 160 rows x 32 halfs per buffer = 640 16B-chunks per buffer, 1280 total
    auto cpB = [&](int kb, int st) {
        const int k0 = kb * CBK;
        const uint32_t stb = sbase + (uint32_t)(st * ST_HALFS) * 2u;
#pragma unroll
        for (int q = 0; q < 3; q++) {
            int idx = tid + 512 * q;
            if (idx < 1280) {
                int hl = idx >= 640;
                int c = idx - (hl ? 640 : 0);
                int n = c >> 2;
                int ch = (c & 3) << 3;   // half offset within row: 0,8,16,24
                const uint16_t* src = (hl ? WloT : WhiT) +
                                      (size_t)(jb + n) * KPAD + k0 + ch;
                uint32_t dst = stb + (uint32_t)((hl ? OFF_BL : OFF_BH) + n * ASTR + ch) * 2u;
                cp16(dst, src);
            }
        }
    };

    // ---- prologue: fill stage 0 ----
    loadA(0);
    cpB(0, 0);
    cp_commit();
    stsA(0);
    cp_wait0();
    __syncthreads();

    for (int kb = 0; kb < NKB; kb++) {
        const int cur = kb & 1;
        const int nxt = cur ^ 1;
        if (kb + 1 < NKB) {
            cpB(kb + 1, nxt);       // async into other stage
            cp_commit();
            loadA(kb + 1);          // LDGs in flight during compute
        }

        // ---- compute on stage cur ----
        const uint32_t stb = sbase + (uint32_t)(cur * ST_HALFS) * 2u;
#pragma unroll
        for (int kk = 0; kk < CBK; kk += 16) {
            uint32_t bhf[5][2], blf[5][2], t4[4];
            ldsm4(t4, stb + (uint32_t)(b_base0 + kk) * 2u);
            bhf[0][0] = t4[0]; bhf[0][1] = t4[1]; bhf[1][0] = t4[2]; bhf[1][1] = t4[3];
            ldsm4(t4, stb + (uint32_t)(b_base1 + kk) * 2u);
            bhf[2][0] = t4[0]; bhf[2][1] = t4[1]; bhf[3][0] = t4[2]; bhf[3][1] = t4[3];
            ldsm2(bhf[4], stb + (uint32_t)(b_base2 + kk) * 2u);
            ldsm4(t4, stb + (uint32_t)(b_base0 + dBL + kk) * 2u);
            blf[0][0] = t4[0]; blf[0][1] = t4[1]; blf[1][0] = t4[2]; blf[1][1] = t4[3];
            ldsm4(t4, stb + (uint32_t)(b_base1 + dBL + kk) * 2u);
            blf[2][0] = t4[0]; blf[2][1] = t4[1]; blf[3][0] = t4[2]; blf[3][1] = t4[3];
            ldsm2(blf[4], stb + (uint32_t)(b_base2 + dBL + kk) * 2u);

#pragma unroll
            for (int f = 0; f < 2; f++) {
                uint32_t ah[4], al[4];
                int ab = (f == 0 ? a_base0 : a_base1) + kk;
                ldsm4(ah, stb + (uint32_t)ab * 2u);
                ldsm4(al, stb + (uint32_t)(ab + dAL) * 2u);
#pragma unroll
                for (int j = 0; j < 5; j++) {
                    mma_bf16(acc[f][j], ah, bhf[j][0], bhf[j][1]);
                    mma_bf16(acc[f][j], ah, blf[j][0], blf[j][1]);
                    mma_bf16(acc[f][j], al, bhf[j][0], bhf[j][1]);
                }
            }
        }

        if (kb + 1 < NKB) {
            stsA(nxt);
            cp_wait0();
        }
        __syncthreads();
    }

    // ---- epilogue: + bias + h0 skip, relu, store ----
#pragma unroll
    for (int f = 0; f < 2; f++) {
#pragma unroll
        for (int j = 0; j < 5; j++) {
            int n0 = jb + wn * 40 + j * 8 + tg * 2;
            if (n0 >= HID) continue;
            float2 bb = *(const float2*)(bias + n0);
#pragma unroll
            for (int half = 0; half < 2; half++) {
                int e = eb + wm * 32 + f * 16 + gp + half * 8;
                float2 hz = *(const float2*)(h0 + (size_t)e * HID + n0);
                float o0 = acc[f][j][half * 2 + 0] + bb.x + hz.x;
                float o1 = acc[f][j][half * 2 + 1] + bb.y + hz.y;
                float2 o = make_float2(fmaxf(o0, 0.f), fmaxf(o1, 0.f));
                *(float2*)(out + (size_t)e * HID + n0) = o;
            }
        }
    }
}

// ---------------- SIMT GEMMs (init, e2n) ----------------

// h0[e] = relu(cat(x[row[e]], edge_attr[e]) @ W_init + b)   K = 80
__global__ void __launch_bounds__(256, 4) k_init(
    const float* __restrict__ x, const float* __restrict__ ea,
    const float* __restrict__ W, const float* __restrict__ bias,
    const int* __restrict__ row, float* __restrict__ out)
{
    __shared__ float As[TM][TK + 1];
    __shared__ float Bs[TK][TN];
    const int eb = blockIdx.y * TM;
    const int jb = blockIdx.x * TN;
    const int tid = threadIdx.x;

    const int lm = tid >> 2;
    const int lk = (tid & 3) << 2;
    const int e_l = eb + lm;
    const float* xp = x  + (size_t)__ldg(row + e_l) * FN;
    const float* ep = ea + (size_t)e_l * FE;

    const int bk = tid >> 4;
    const int bj = (tid & 15) << 2;
    const bool bj_ok = (jb + bj) < HID;

    const int tm = (tid >> 4) << 2;
    const int tn = (tid & 15) << 2;

    float acc[4][4] = {};

    for (int k0 = 0; k0 < FN + FE; k0 += TK) {
        int ka = k0 + lk;
        float4 av = (ka < FN) ? *(const float4*)(xp + ka)
                              : *(const float4*)(ep + (ka - FN));
        As[lm][lk + 0] = av.x; As[lm][lk + 1] = av.y;
        As[lm][lk + 2] = av.z; As[lm][lk + 3] = av.w;

        int kb = k0 + bk;
        float4 wv = make_float4(0.f, 0.f, 0.f, 0.f);
        if (bj_ok) wv = *(const float4*)(W + (size_t)kb * HID + jb + bj);
        *(float4*)&Bs[bk][bj] = wv;

        __syncthreads();
#pragma unroll
        for (int k = 0; k < TK; k++) {
            float4 bv = *(const float4*)&Bs[k][tn];
            float a0 = As[tm + 0][k], a1 = As[tm + 1][k];
            float a2 = As[tm + 2][k], a3 = As[tm + 3][k];
            acc[0][0] += a0 * bv.x; acc[0][1] += a0 * bv.y; acc[0][2] += a0 * bv.z; acc[0][3] += a0 * bv.w;
            acc[1][0] += a1 * bv.x; acc[1][1] += a1 * bv.y; acc[1][2] += a1 * bv.z; acc[1][3] += a1 * bv.w;
            acc[2][0] += a2 * bv.x; acc[2][1] += a2 * bv.y; acc[2][2] += a2 * bv.z; acc[2][3] += a2 * bv.w;
            acc[3][0] += a3 * bv.x; acc[3][1] += a3 * bv.y; acc[3][2] += a3 * bv.z; acc[3][3] += a3 * bv.w;
        }
        __syncthreads();
    }

    const int j = jb + tn;
    if (j < HID) {
        float4 bb = *(const float4*)(bias + j);
#pragma unroll
        for (int i = 0; i < 4; i++) {
            int e = eb + tm + i;
            float4 o;
            o.x = fmaxf(acc[i][0] + bb.x, 0.f);
            o.y = fmaxf(acc[i][1] + bb.y, 0.f);
            o.z = fmaxf(acc[i][2] + bb.z, 0.f);
            o.w = fmaxf(acc[i][3] + bb.w, 0.f);
            *(float4*)(out + (size_t)e * HID + j) = o;
        }
    }
}

// hn[n] = relu(cat(x[n], s[n]) @ W_e2n + b)   K = 364
__global__ void __launch_bounds__(256, 4) k_e2n(
    const float* __restrict__ x, const float* __restrict__ s,
    const float* __restrict__ W, const float* __restrict__ bias,
    float* __restrict__ out)
{
    __shared__ float As[TM][TK + 1];
    __shared__ float Bs[TK][TN];
    const int nb = blockIdx.y * TM;
    const int jb = blockIdx.x * TN;
    const int tid = threadIdx.x;
    const int KT = FN + HID;

    const int lm = tid >> 2;
    const int lk = (tid & 3) << 2;
    const int n_l = nb + lm;
    const int n_c = n_l < NN ? n_l : NN - 1;
    const float* xp = x + (size_t)n_c * FN;
    const float* sp = s + (size_t)n_c * HID;

    const int bk = tid >> 4;
    const int bj = (tid & 15) << 2;
    const bool bj_ok = (jb + bj) < HID;

    const int tm = (tid >> 4) << 2;
    const int tn = (tid & 15) << 2;

    float acc[4][4] = {};

    for (int k0 = 0; k0 < KT; k0 += TK) {
        int ka = k0 + lk;
        float4 av = make_float4(0.f, 0.f, 0.f, 0.f);
        if (ka < FN)      av = *(const float4*)(xp + ka);
        else if (ka < KT) av = *(const float4*)(sp + (ka - FN));
        As[lm][lk + 0] = av.x; As[lm][lk + 1] = av.y;
        As[lm][lk + 2] = av.z; As[lm][lk + 3] = av.w;

        int kb = k0 + bk;
        float4 wv = make_float4(0.f, 0.f, 0.f, 0.f);
        if (kb < KT && bj_ok) wv = *(const float4*)(W + (size_t)kb * HID + jb + bj);
        *(float4*)&Bs[bk][bj] = wv;

        __syncthreads();
#pragma unroll
        for (int k = 0; k < TK; k++) {
            float4 bv = *(const float4*)&Bs[k][tn];
            float a0 = As[tm + 0][k], a1 = As[tm + 1][k];
            float a2 = As[tm + 2][k], a3 = As[tm + 3][k];
            acc[0][0] += a0 * bv.x; acc[0][1] += a0 * bv.y; acc[0][2] += a0 * bv.z; acc[0][3] += a0 * bv.w;
            acc[1][0] += a1 * bv.x; acc[1][1] += a1 * bv.y; acc[1][2] += a1 * bv.z; acc[1][3] += a1 * bv.w;
            acc[2][0] += a2 * bv.x; acc[2][1] += a2 * bv.y; acc[2][2] += a2 * bv.z; acc[2][3] += a2 * bv.w;
            acc[3][0] += a3 * bv.x; acc[3][1] += a3 * bv.y; acc[3][2] += a3 * bv.z; acc[3][3] += a3 * bv.w;
        }
        __syncthreads();
    }

    const int j = jb + tn;
    if (j < HID) {
        float4 bb = *(const float4*)(bias + j);
#pragma unroll
        for (int i = 0; i < 4; i++) {
            int n = nb + tm + i;
            if (n >= NN) break;
            float4 o;
            o.x = fmaxf(acc[i][0] + bb.x, 0.f);
            o.y = fmaxf(acc[i][1] + bb.y, 0.f);
            o.z = fmaxf(acc[i][2] + bb.z, 0.f);
            o.w = fmaxf(acc[i][3] + bb.w, 0.f);
            *(float4*)(out + (size_t)n * HID + j) = o;
        }
    }
}

// ---------------- launch ----------------
extern "C" void kernel_launch(void* const* d_in, const int* in_sizes, int n_in,
                              void* d_out, int out_size) {
    const float* x        = (const float*)d_in[0];
    const float* edge_attr= (const float*)d_in[1];
    const int*   edge_idx = (const int*)  d_in[2];
    const int*   batch    = (const int*)  d_in[3];
    const float* W_init   = (const float*)d_in[4];
    const float* b_init   = (const float*)d_in[5];
    const float* W_convs  = (const float*)d_in[6];
    const float* b_convs  = (const float*)d_in[7];
    const float* W_e2n    = (const float*)d_in[8];
    const float* b_e2n    = (const float*)d_in[9];
    const float* W_ffn    = (const float*)d_in[10];
    const float* b_ffn    = (const float*)d_in[11];
    float* out = (float*)d_out;

    const int* row = edge_idx;
    const int* col = edge_idx + NE;

    float *h0, *hA, *hB, *a, *hn, *pool;
    uint16_t *WhiT, *WloT;
    cudaGetSymbolAddress((void**)&h0,   g_h0);
    cudaGetSymbolAddress((void**)&hA,   g_hA);
    cudaGetSymbolAddress((void**)&hB,   g_hB);
    cudaGetSymbolAddress((void**)&a,    g_a);
    cudaGetSymbolAddress((void**)&hn,   g_hn);
    cudaGetSymbolAddress((void**)&pool, g_pool);
    cudaGetSymbolAddress((void**)&WhiT, g_WhiT);
    cudaGetSymbolAddress((void**)&WloT, g_WloT);

    cudaFuncSetAttribute(k_conv_mma, cudaFuncAttributeMaxDynamicSharedMemorySize,
                         CONV_SMEM);

    const int a4 = NN * (HID / 4);
    const int e4 = NE * (HID / 4);
    const int p4 = NG * (HID / 4);

    // split conv weights (bf16 hi/lo, transposed [n][k], padded to 320x320)
    const int wtot = NDEPTH * NPR * KPAD;
    k_splitW<<<(wtot + 255) / 256, 256>>>(W_convs, WhiT, WloT);

    // h0 = relu(edge_init(cat(x[row], edge_attr)))
    const dim3 init_grid((HID + TN - 1) / TN, NE / TM);
    k_init<<<init_grid, 256>>>(x, edge_attr, W_init, b_init, row, h0);

    const dim3 conv_grid(2, NE / CBM);  // (2, 2500)
    const float* hcur = h0;
    float* bufs[2] = {hA, hB};
    for (int l = 0; l < NDEPTH; l++) {
        k_zero<<<(a4 + 255) / 256, 256>>>((float4*)a, a4);
        k_scatter_edges<<<(e4 + 255) / 256, 256>>>((const float4*)hcur, col, a);
        float* hnext = bufs[l & 1];
        k_conv_mma<<<conv_grid, 512, CONV_SMEM>>>(a, hcur, h0,
                                       WhiT + (size_t)l * NPR * KPAD,
                                       WloT + (size_t)l * NPR * KPAD,
                                       b_convs + (size_t)l * HID, row, hnext);
        hcur = hnext;
    }

    // final segment sum -> s (reuse a), node MLP, pooling, FFN
    k_zero<<<(a4 + 255) / 256, 256>>>((float4*)a, a4);
    k_scatter_edges<<<(e4 + 255) / 256, 256>>>((const float4*)hcur, col, a);

    const dim3 e2n_grid((HID + TN - 1) / TN, (NN + TM - 1) / TM);
    k_e2n<<<e2n_grid, 256>>>(x, a, W_e2n, b_e2n, hn);

    k_zero<<<(p4 + 255) / 256, 256>>>((float4*)pool, p4);
    k_scatter_pool<<<(a4 + 255) / 256, 256>>>((const float4*)hn, batch, pool);
    k_ffn<<<NG, 128>>>(pool, W_ffn, b_ffn, out);
}

// round 16
// speedup vs baseline: 1.6324x; 1.0855x over previous
#include <cuda_runtime.h>
#include <cuda_bf16.h>
#include <cstdint>

#define NN 20000
#define NE 320000
#define FN 64
#define FE 16
#define HID 300
#define NDEPTH 3
#define NG 128

// SIMT GEMM tiles (e2n)
#define TM 64
#define TN 64
#define TK 16

// edge MMA tiles
#define CBM 128
#define CBN 160
#define CBK 32
#define KPC 320            // conv K padded
#define KPI 96             // init K padded (80 -> 96)
#define NPR 320            // W rows padded (HID=300 -> 320)
#define ASTR 40            // padded k-stride in halfs

// dynamic smem: 2 stages, per stage (halfs): Ah 5120 | Al 5120 | Bh 6400 | Bl 6400
#define ST_HALFS 23040
#define OFF_AL 5120
#define OFF_BH 10240
#define OFF_BL 16640
#define CONV_SMEM (2 * ST_HALFS * 2)   // 92160 bytes

// ---------------- static scratch (no runtime allocation allowed) ----------------
__device__ __align__(256) float g_h0[(size_t)NE * HID];
__device__ __align__(256) float g_hA[(size_t)NE * HID];
__device__ __align__(256) float g_hB[(size_t)NE * HID];
__device__ __align__(256) float g_a0[(size_t)NN * HID];
__device__ __align__(256) float g_a1[(size_t)NN * HID];
__device__ __align__(256) float g_pool[(size_t)NG * HID];
__device__ __align__(256) uint16_t g_WcHi[(size_t)NDEPTH * NPR * KPC];
__device__ __align__(256) uint16_t g_WcLo[(size_t)NDEPTH * NPR * KPC];
__device__ __align__(256) uint16_t g_WiHi[(size_t)NPR * KPI];
__device__ __align__(256) uint16_t g_WiLo[(size_t)NPR * KPI];

// ---------------- helpers ----------------
__device__ __forceinline__ uint16_t f2bf_bits(float v) {
    __nv_bfloat16 b = __float2bfloat16(v);
    return *reinterpret_cast<uint16_t*>(&b);
}
__device__ __forceinline__ float bf_bits2f(uint16_t u) {
    __nv_bfloat16 b = *reinterpret_cast<__nv_bfloat16*>(&u);
    return __bfloat162float(b);
}

__device__ __forceinline__ void mma_bf16(float* d, const uint32_t* a,
                                         uint32_t b0, uint32_t b1) {
    asm volatile(
        "mma.sync.aligned.m16n8k16.row.col.f32.bf16.bf16.f32 "
        "{%0,%1,%2,%3}, {%4,%5,%6,%7}, {%8,%9}, {%0,%1,%2,%3};"
        : "+f"(d[0]), "+f"(d[1]), "+f"(d[2]), "+f"(d[3])
        : "r"(a[0]), "r"(a[1]), "r"(a[2]), "r"(a[3]), "r"(b0), "r"(b1));
}

__device__ __forceinline__ void ldsm4(uint32_t* r, uint32_t addr) {
    asm volatile("ldmatrix.sync.aligned.m8n8.x4.shared.b16 {%0,%1,%2,%3}, [%4];"
                 : "=r"(r[0]), "=r"(r[1]), "=r"(r[2]), "=r"(r[3]) : "r"(addr));
}
__device__ __forceinline__ void ldsm2(uint32_t* r, uint32_t addr) {
    asm volatile("ldmatrix.sync.aligned.m8n8.x2.shared.b16 {%0,%1}, [%2];"
                 : "=r"(r[0]), "=r"(r[1]) : "r"(addr));
}

__device__ __forceinline__ void cp16(uint32_t dst, const void* src) {
    asm volatile("cp.async.cg.shared.global [%0], [%1], 16;" :: "r"(dst), "l"(src));
}
__device__ __forceinline__ void cp_commit() { asm volatile("cp.async.commit_group;"); }
__device__ __forceinline__ void cp_wait0()  { asm volatile("cp.async.wait_group 0;"); }

__device__ __forceinline__ void red_v4(float* dst, float4 v) {
    asm volatile("red.global.add.v4.f32 [%0], {%1,%2,%3,%4};" ::
                 "l"(dst), "f"(v.x), "f"(v.y), "f"(v.z), "f"(v.w) : "memory");
}
__device__ __forceinline__ void red_v2(float* dst, float2 v) {
    asm volatile("red.global.add.v2.f32 [%0], {%1,%2};" ::
                 "l"(dst), "f"(v.x), "f"(v.y) : "memory");
}

// ---------------- utility kernels ----------------
__global__ void k_zero(float4* p, int n4) {
    int i = blockIdx.x * blockDim.x + threadIdx.x;
    if (i < n4) p[i] = make_float4(0.f, 0.f, 0.f, 0.f);
}

// split conv weights -> transposed padded bf16 hi/lo [l][n(320)][k(320)]
__global__ void k_splitWc(const float* __restrict__ W,
                          uint16_t* __restrict__ Whi, uint16_t* __restrict__ Wlo) {
    int idx = blockIdx.x * blockDim.x + threadIdx.x;
    const int total = NDEPTH * NPR * KPC;
    if (idx >= total) return;
    int l = idx / (NPR * KPC);
    int rem = idx - l * (NPR * KPC);
    int n = rem / KPC;
    int k = rem - n * KPC;
    float v = (k < HID && n < HID) ? W[(size_t)l * HID * HID + (size_t)k * HID + n] : 0.f;
    uint16_t hb = f2bf_bits(v);
    float lo = v - bf_bits2f(hb);
    Whi[idx] = hb;
    Wlo[idx] = f2bf_bits(lo);
}

// split init weights W_init[80][300] -> [n(320)][k(96)]
__global__ void k_splitWi(const float* __restrict__ W,
                          uint16_t* __restrict__ Whi, uint16_t* __restrict__ Wlo) {
    int idx = blockIdx.x * blockDim.x + threadIdx.x;
    const int total = NPR * KPI;
    if (idx >= total) return;
    int n = idx / KPI;
    int k = idx - n * KPI;
    float v = (k < FN + FE && n < HID) ? W[(size_t)k * HID + n] : 0.f;
    uint16_t hb = f2bf_bits(v);
    float lo = v - bf_bits2f(hb);
    Whi[idx] = hb;
    Wlo[idx] = f2bf_bits(lo);
}

__global__ void k_ffn(const float* __restrict__ pool, const float* __restrict__ W,
                      const float* __restrict__ b, float* __restrict__ out) {
    __shared__ float red[128];
    int g = blockIdx.x;
    float s = 0.f;
    for (int j = threadIdx.x; j < HID; j += 128)
        s += pool[(size_t)g * HID + j] * W[j];
    red[threadIdx.x] = s;
    __syncthreads();
    for (int k = 64; k > 0; k >>= 1) {
        if (threadIdx.x < k) red[threadIdx.x] += red[threadIdx.x + k];
        __syncthreads();
    }
    if (threadIdx.x == 0) out[g] = red[0] + b[0];
}

// ---------------- edge GEMM via tensor cores (split-bf16, 3-MMA) ----------------
// CONV: out[e] = relu((a1p[row[e]] - a2p[e^1]) @ W + b + h0[e]); scatter out -> scat
// INIT: out[e] = relu(cat(a1p[row[e]](x), a2p[e](edge_attr)) @ W + b); scatter -> scat
template<int KP, bool IS_CONV>
__global__ void __launch_bounds__(512, 1) k_edge_mma(
    const float* __restrict__ a1p, const float* __restrict__ a2p,
    const float* __restrict__ h0, const uint16_t* __restrict__ Whi,
    const uint16_t* __restrict__ Wlo, const float* __restrict__ bias,
    const int* __restrict__ row, const int* __restrict__ col,
    float* __restrict__ out, float* __restrict__ scat)
{
    constexpr int NKB = KP / CBK;
    extern __shared__ __align__(256) uint16_t smem[];
    __shared__ int rows_s[CBM];
    __shared__ int cols_s[CBM];

    const int tid = threadIdx.x;
    const int eb = blockIdx.y * CBM;
    const int jb = blockIdx.x * CBN;

    const uint32_t sbase = (uint32_t)__cvta_generic_to_shared(smem);

    if (tid < CBM) {
        rows_s[tid] = __ldg(row + eb + tid);
        cols_s[tid] = __ldg(col + eb + tid);
    }
    __syncthreads();

    // A staging: thread covers row ai, 8 consecutive k at ak0
    const int ai = tid >> 2;
    const int ak0 = (tid & 3) << 3;
    const float* ap;
    const float* hp;
    if constexpr (IS_CONV) {
        ap = a1p + (size_t)rows_s[ai] * HID;
        hp = a2p + (size_t)((eb + ai) ^ 1) * HID;
    } else {
        ap = a1p + (size_t)rows_s[ai] * FN;       // x[row[e]]
        hp = a2p + (size_t)(eb + ai) * FE;        // edge_attr[e]
    }

    // warp/frag mapping: 16 warps = wm(4) x wn(4); warp tile 32(M) x 40(N)
    const int wid = tid >> 5, lane = tid & 31;
    const int wm = wid >> 2, wn = wid & 3;
    const int gp = lane >> 2, tg = lane & 3;

    float acc[2][5][4] = {};
    float rA[8];

    const int lg = lane >> 3;
    const int l7 = lane & 7;
    int a_base0 = (wm * 32 + 0  + l7 + (lg & 1) * 8) * ASTR + (lg >> 1) * 8;
    int a_base1 = (wm * 32 + 16 + l7 + (lg & 1) * 8) * ASTR + (lg >> 1) * 8;
    int b_base0 = OFF_BH + (wn * 40 + (0 + (lg >> 1)) * 8 + l7) * ASTR + (lg & 1) * 8;
    int b_base1 = OFF_BH + (wn * 40 + (2 + (lg >> 1)) * 8 + l7) * ASTR + (lg & 1) * 8;
    int b_base2 = OFF_BH + (wn * 40 + 32 + l7) * ASTR + (lg & 1) * 8;
    const int dBL = OFF_BL - OFF_BH;
    const int dAL = OFF_AL;

    auto loadA = [&](int kb) {
        const int k0 = kb * CBK;
#pragma unroll
        for (int v = 0; v < 2; v++) {
            int kg = k0 + ak0 + v * 4;
            if constexpr (IS_CONV) {
                float4 av, hv;
                if (kg < HID) {
                    av = *(const float4*)(ap + kg);
                    hv = *(const float4*)(hp + kg);
                } else {
                    av = make_float4(0.f, 0.f, 0.f, 0.f);
                    hv = av;
                }
                rA[v * 4 + 0] = av.x - hv.x; rA[v * 4 + 1] = av.y - hv.y;
                rA[v * 4 + 2] = av.z - hv.z; rA[v * 4 + 3] = av.w - hv.w;
            } else {
                float4 av;
                if (kg < FN)            av = *(const float4*)(ap + kg);
                else if (kg < FN + FE)  av = *(const float4*)(hp + (kg - FN));
                else                    av = make_float4(0.f, 0.f, 0.f, 0.f);
                rA[v * 4 + 0] = av.x; rA[v * 4 + 1] = av.y;
                rA[v * 4 + 2] = av.z; rA[v * 4 + 3] = av.w;
            }
        }
    };

    auto stsA = [&](int st) {
        uint16_t* Ah = smem + st * ST_HALFS;
        uint32_t ph[4], pl[4];
#pragma unroll
        for (int j = 0; j < 8; j += 2) {
            float v0 = rA[j], v1 = rA[j + 1];
            uint16_t h0b = f2bf_bits(v0);
            uint16_t l0b = f2bf_bits(v0 - bf_bits2f(h0b));
            uint16_t h1b = f2bf_bits(v1);
            uint16_t l1b = f2bf_bits(v1 - bf_bits2f(h1b));
            ph[j >> 1] = (uint32_t)h0b | ((uint32_t)h1b << 16);
            pl[j >> 1] = (uint32_t)l0b | ((uint32_t)l1b << 16);
        }
        int kc = ai * ASTR + ak0;
        *(uint2*)&Ah[kc]           = make_uint2(ph[0], ph[1]);
        *(uint2*)&Ah[kc + 4]       = make_uint2(ph[2], ph[3]);
        *(uint2*)&Ah[dAL + kc]     = make_uint2(pl[0], pl[1]);
        *(uint2*)&Ah[dAL + kc + 4] = make_uint2(pl[2], pl[3]);
    };

    auto cpB = [&](int kb, int st) {
        const int k0 = kb * CBK;
        const uint32_t stb = sbase + (uint32_t)(st * ST_HALFS) * 2u;
#pragma unroll
        for (int q = 0; q < 3; q++) {
            int idx = tid + 512 * q;
            if (idx < 1280) {
                int hl = idx >= 640;
                int c = idx - (hl ? 640 : 0);
                int n = c >> 2;
                int ch = (c & 3) << 3;
                const uint16_t* src = (hl ? Wlo : Whi) +
                                      (size_t)(jb + n) * KP + k0 + ch;
                uint32_t dst = stb + (uint32_t)((hl ? OFF_BL : OFF_BH) + n * ASTR + ch) * 2u;
                cp16(dst, src);
            }
        }
    };

    // ---- prologue: fill stage 0 ----
    loadA(0);
    cpB(0, 0);
    cp_commit();
    stsA(0);
    cp_wait0();
    __syncthreads();

    for (int kb = 0; kb < NKB; kb++) {
        const int cur = kb & 1;
        const int nxt = cur ^ 1;
        if (kb + 1 < NKB) {
            cpB(kb + 1, nxt);
            cp_commit();
            loadA(kb + 1);
        }

        const uint32_t stb = sbase + (uint32_t)(cur * ST_HALFS) * 2u;
#pragma unroll
        for (int kk = 0; kk < CBK; kk += 16) {
            uint32_t bhf[5][2], blf[5][2], t4[4];
            ldsm4(t4, stb + (uint32_t)(b_base0 + kk) * 2u);
            bhf[0][0] = t4[0]; bhf[0][1] = t4[1]; bhf[1][0] = t4[2]; bhf[1][1] = t4[3];
            ldsm4(t4, stb + (uint32_t)(b_base1 + kk) * 2u);
            bhf[2][0] = t4[0]; bhf[2][1] = t4[1]; bhf[3][0] = t4[2]; bhf[3][1] = t4[3];
            ldsm2(bhf[4], stb + (uint32_t)(b_base2 + kk) * 2u);
            ldsm4(t4, stb + (uint32_t)(b_base0 + dBL + kk) * 2u);
            blf[0][0] = t4[0]; blf[0][1] = t4[1]; blf[1][0] = t4[2]; blf[1][1] = t4[3];
            ldsm4(t4, stb + (uint32_t)(b_base1 + dBL + kk) * 2u);
            blf[2][0] = t4[0]; blf[2][1] = t4[1]; blf[3][0] = t4[2]; blf[3][1] = t4[3];
            ldsm2(blf[4], stb + (uint32_t)(b_base2 + dBL + kk) * 2u);

#pragma unroll
            for (int f = 0; f < 2; f++) {
                uint32_t ah[4], al[4];
                int ab = (f == 0 ? a_base0 : a_base1) + kk;
                ldsm4(ah, stb + (uint32_t)ab * 2u);
                ldsm4(al, stb + (uint32_t)(ab + dAL) * 2u);
#pragma unroll
                for (int j = 0; j < 5; j++) {
                    mma_bf16(acc[f][j], ah, bhf[j][0], bhf[j][1]);
                    mma_bf16(acc[f][j], ah, blf[j][0], blf[j][1]);
                    mma_bf16(acc[f][j], al, bhf[j][0], bhf[j][1]);
                }
            }
        }

        if (kb + 1 < NKB) {
            stsA(nxt);
            cp_wait0();
        }
        __syncthreads();
    }

    // ---- epilogue: + bias (+ h0 skip), relu, store, fused scatter ----
#pragma unroll
    for (int f = 0; f < 2; f++) {
#pragma unroll
        for (int j = 0; j < 5; j++) {
            int n0 = jb + wn * 40 + j * 8 + tg * 2;
            if (n0 >= HID) continue;
            float2 bb = *(const float2*)(bias + n0);
#pragma unroll
            for (int half = 0; half < 2; half++) {
                int m = wm * 32 + f * 16 + gp + half * 8;
                int e = eb + m;
                float o0 = acc[f][j][half * 2 + 0] + bb.x;
                float o1 = acc[f][j][half * 2 + 1] + bb.y;
                if constexpr (IS_CONV) {
                    float2 hz = *(const float2*)(h0 + (size_t)e * HID + n0);
                    o0 += hz.x; o1 += hz.y;
                }
                float2 o = make_float2(fmaxf(o0, 0.f), fmaxf(o1, 0.f));
                *(float2*)(out + (size_t)e * HID + n0) = o;
                red_v2(scat + (size_t)cols_s[m] * HID + n0, o);
            }
        }
    }
}

// ---------------- e2n with fused pooling ----------------
// pool[batch[n]] += relu(cat(x[n], s[n]) @ W_e2n + b)   K = 364
__global__ void __launch_bounds__(256, 4) k_e2n(
    const float* __restrict__ x, const float* __restrict__ s,
    const float* __restrict__ W, const float* __restrict__ bias,
    const int* __restrict__ batch, float* __restrict__ pool)
{
    __shared__ float As[TM][TK + 1];
    __shared__ float Bs[TK][TN];
    __shared__ int batch_s[TM];
    const int nb = blockIdx.y * TM;
    const int jb = blockIdx.x * TN;
    const int tid = threadIdx.x;
    const int KT = FN + HID;

    if (tid < TM) {
        int n = nb + tid;
        batch_s[tid] = (n < NN) ? __ldg(batch + n) : 0;
    }

    const int lm = tid >> 2;
    const int lk = (tid & 3) << 2;
    const int n_l = nb + lm;
    const int n_c = n_l < NN ? n_l : NN - 1;
    const float* xp = x + (size_t)n_c * FN;
    const float* sp = s + (size_t)n_c * HID;

    const int bk = tid >> 4;
    const int bj = (tid & 15) << 2;
    const bool bj_ok = (jb + bj) < HID;

    const int tm = (tid >> 4) << 2;
    const int tn = (tid & 15) << 2;

    float acc[4][4] = {};

    for (int k0 = 0; k0 < KT; k0 += TK) {
        int ka = k0 + lk;
        float4 av = make_float4(0.f, 0.f, 0.f, 0.f);
        if (ka < FN)      av = *(const float4*)(xp + ka);
        else if (ka < KT) av = *(const float4*)(sp + (ka - FN));
        As[lm][lk + 0] = av.x; As[lm][lk + 1] = av.y;
        As[lm][lk + 2] = av.z; As[lm][lk + 3] = av.w;

        int kb = k0 + bk;
        float4 wv = make_float4(0.f, 0.f, 0.f, 0.f);
        if (kb < KT && bj_ok) wv = *(const float4*)(W + (size_t)kb * HID + jb + bj);
        *(float4*)&Bs[bk][bj] = wv;

        __syncthreads();
#pragma unroll
        for (int k = 0; k < TK; k++) {
            float4 bv = *(const float4*)&Bs[k][tn];
            float a0 = As[tm + 0][k], a1 = As[tm + 1][k];
            float a2 = As[tm + 2][k], a3 = As[tm + 3][k];
            acc[0][0] += a0 * bv.x; acc[0][1] += a0 * bv.y; acc[0][2] += a0 * bv.z; acc[0][3] += a0 * bv.w;
            acc[1][0] += a1 * bv.x; acc[1][1] += a1 * bv.y; acc[1][2] += a1 * bv.z; acc[1][3] += a1 * bv.w;
            acc[2][0] += a2 * bv.x; acc[2][1] += a2 * bv.y; acc[2][2] += a2 * bv.z; acc[2][3] += a2 * bv.w;
            acc[3][0] += a3 * bv.x; acc[3][1] += a3 * bv.y; acc[3][2] += a3 * bv.z; acc[3][3] += a3 * bv.w;
        }
        __syncthreads();
    }

    const int j = jb + tn;
    if (j < HID) {
        float4 bb = *(const float4*)(bias + j);
#pragma unroll
        for (int i = 0; i < 4; i++) {
            int n = nb + tm + i;
            if (n >= NN) break;
            float4 o;
            o.x = fmaxf(acc[i][0] + bb.x, 0.f);
            o.y = fmaxf(acc[i][1] + bb.y, 0.f);
            o.z = fmaxf(acc[i][2] + bb.z, 0.f);
            o.w = fmaxf(acc[i][3] + bb.w, 0.f);
            red_v4(pool + (size_t)batch_s[tm + i] * HID + j, o);
        }
    }
}

// ---------------- launch ----------------
extern "C" void kernel_launch(void* const* d_in, const int* in_sizes, int n_in,
                              void* d_out, int out_size) {
    const float* x        = (const float*)d_in[0];
    const float* edge_attr= (const float*)d_in[1];
    const int*   edge_idx = (const int*)  d_in[2];
    const int*   batch    = (const int*)  d_in[3];
    const float* W_init   = (const float*)d_in[4];
    const float* b_init   = (const float*)d_in[5];
    const float* W_convs  = (const float*)d_in[6];
    const float* b_convs  = (const float*)d_in[7];
    const float* W_e2n    = (const float*)d_in[8];
    const float* b_e2n    = (const float*)d_in[9];
    const float* W_ffn    = (const float*)d_in[10];
    const float* b_ffn    = (const float*)d_in[11];
    float* out = (float*)d_out;

    const int* row = edge_idx;
    const int* col = edge_idx + NE;

    float *h0, *hA, *hB, *a0, *a1, *pool;
    uint16_t *WcHi, *WcLo, *WiHi, *WiLo;
    cudaGetSymbolAddress((void**)&h0,   g_h0);
    cudaGetSymbolAddress((void**)&hA,   g_hA);
    cudaGetSymbolAddress((void**)&hB,   g_hB);
    cudaGetSymbolAddress((void**)&a0,   g_a0);
    cudaGetSymbolAddress((void**)&a1,   g_a1);
    cudaGetSymbolAddress((void**)&pool, g_pool);
    cudaGetSymbolAddress((void**)&WcHi, g_WcHi);
    cudaGetSymbolAddress((void**)&WcLo, g_WcLo);
    cudaGetSymbolAddress((void**)&WiHi, g_WiHi);
    cudaGetSymbolAddress((void**)&WiLo, g_WiLo);

    cudaFuncSetAttribute(k_edge_mma<KPC, true>,
                         cudaFuncAttributeMaxDynamicSharedMemorySize, CONV_SMEM);
    cudaFuncSetAttribute(k_edge_mma<KPI, false>,
                         cudaFuncAttributeMaxDynamicSharedMemorySize, CONV_SMEM);

    const int a4 = NN * (HID / 4);
    const int p4 = NG * (HID / 4);

    // weight prep
    const int wct = NDEPTH * NPR * KPC;
    k_splitWc<<<(wct + 255) / 256, 256>>>(W_convs, WcHi, WcLo);
    const int wit = NPR * KPI;
    k_splitWi<<<(wit + 255) / 256, 256>>>(W_init, WiHi, WiLo);

    const dim3 egrid(2, NE / CBM);  // (2, 2500)

    // init: h0 = relu(...), scatter h0 -> a0
    k_zero<<<(a4 + 255) / 256, 256>>>((float4*)a0, a4);
    k_edge_mma<KPI, false><<<egrid, 512, CONV_SMEM>>>(
        x, edge_attr, nullptr, WiHi, WiLo, b_init, row, col, h0, a0);

    float* abufs[2] = {a0, a1};
    float* hbufs[2] = {hA, hB};
    const float* hcur = h0;
    for (int l = 0; l < NDEPTH; l++) {
        float* acur = abufs[l & 1];
        float* anxt = abufs[(l + 1) & 1];
        float* hnext = hbufs[l & 1];
        k_zero<<<(a4 + 255) / 256, 256>>>((float4*)anxt, a4);
        k_edge_mma<KPC, true><<<egrid, 512, CONV_SMEM>>>(
            acur, hcur, h0, WcHi + (size_t)l * NPR * KPC,
            WcLo + (size_t)l * NPR * KPC, b_convs + (size_t)l * HID,
            row, col, hnext, anxt);
        hcur = hnext;
    }
    // after loop: final scatter landed in abufs[NDEPTH & 1] = a1

    k_zero<<<(p4 + 255) / 256, 256>>>((float4*)pool, p4);
    const dim3 e2n_grid((HID + TN - 1) / TN, (NN + TM - 1) / TM);
    k_e2n<<<e2n_grid, 256>>>(x, abufs[NDEPTH & 1], W_e2n, b_e2n, batch, pool);

    k_ffn<<<NG, 128>>>(pool, W_ffn, b_ffn, out);
}